// round 1
// baseline (speedup 1.0000x reference)
#include <cuda_runtime.h>
#include <cuda_bf16.h>

// ---------------------------------------------------------------------------
// BipartiteGATConv
//   src_feat = x_src @ W_src                        [N_src, 128]
//   alpha_src[n,h] = dot(src_feat[n,h,:], att_src[h,:])   (fused epilogue)
//   alpha_dst = x_dst @ v_dst, v_dst[k,h] = sum_d W_dst[k,h*32+d]*att_dst[h,d]
//   out = x_dst @ W_self + b_self                   (written directly to d_out)
//   per-edge: a = leaky(alpha_src[s]+alpha_dst[d]); e = exp(a)
//   a_sum[d,h] += e  (red.v4)
//   out[d,:] += (e / (a_sum[d,h]+1e-16)) * src_feat[s,:]   (red.v4, warp/edge)
// Softmax max-subtraction skipped: ratio is shift-invariant and alphas are tiny.
// ---------------------------------------------------------------------------

#define MAX_N   50000
#define MAX_E   800000
#define FDIM    128
#define HEADS   4

__device__ __align__(16) float g_feat[MAX_N * FDIM];    // src_feat
__device__ __align__(16) float g_asrc[MAX_N * HEADS];
__device__ __align__(16) float g_adst[MAX_N * HEADS];
__device__ __align__(16) float g_asum[MAX_N * HEADS];
__device__ __align__(16) float g_v[FDIM * HEADS];       // folded W_dst*att_dst

__device__ __forceinline__ void red_add_v4(float* addr, float4 v) {
    asm volatile("red.global.add.v4.f32 [%0], {%1,%2,%3,%4};"
                 :: "l"(addr), "f"(v.x), "f"(v.y), "f"(v.z), "f"(v.w)
                 : "memory");
}

__device__ __forceinline__ float leaky02(float z) {
    return z > 0.f ? z : 0.2f * z;
}

// ---------------- tiny fold: v_dst[k,h] = sum_d W_dst[k,h*32+d]*att_dst[h,d]
__global__ void fold_v_kernel(const float* __restrict__ W_dst,
                              const float* __restrict__ att_dst) {
    int k = threadIdx.x;                 // 128 threads
    if (k >= FDIM) return;
    #pragma unroll
    for (int h = 0; h < HEADS; h++) {
        float s = 0.f;
        #pragma unroll 8
        for (int d = 0; d < 32; d++)
            s += W_dst[k * FDIM + h * 32 + d] * att_dst[h * 32 + d];
        g_v[k * HEADS + h] = s;
    }
}

// ---------------- zero a_sum
__global__ void zero_asum_kernel(int n) {
    int i = blockIdx.x * blockDim.x + threadIdx.x;
    if (i < n) g_asum[i] = 0.f;
}

// ---------------- GEMM for src: feat + alpha_src (fused att epilogue)
// block = 256 (8 warps); each warp does 4 rows x 128 cols; W in smem.
#define GW 8
#define RPW 4
__global__ __launch_bounds__(256, 2)
void gemm_src_kernel(const float* __restrict__ x,
                     const float* __restrict__ W,
                     const float* __restrict__ att,
                     int nrows) {
    extern __shared__ float sm[];
    float* Wsm   = sm;              // 128*128
    float* attsm = sm + FDIM * FDIM;  // 128
    __shared__ float xs[GW][RPW][FDIM];

    int tid = threadIdx.x;
    float4* Wsm4 = (float4*)Wsm;
    const float4* W4 = (const float4*)W;
    for (int i = tid; i < FDIM * (FDIM / 4); i += 256) Wsm4[i] = W4[i];
    if (tid < FDIM) attsm[tid] = att[tid];
    __syncthreads();

    int warp = tid >> 5, lane = tid & 31;
    int row0 = (blockIdx.x * GW + warp) * RPW;
    if (row0 >= nrows) return;

    for (int i = lane; i < RPW * FDIM; i += 32) {
        int r = i >> 7, k = i & 127;
        int row = row0 + r;
        xs[warp][r][k] = (row < nrows) ? x[row * FDIM + k] : 0.f;
    }
    __syncwarp();

    float acc[RPW][4] = {};
    #pragma unroll 4
    for (int k = 0; k < FDIM; k++) {
        float4 w = Wsm4[k * 32 + lane];
        #pragma unroll
        for (int r = 0; r < RPW; r++) {
            float xv = xs[warp][r][k];
            acc[r][0] += xv * w.x; acc[r][1] += xv * w.y;
            acc[r][2] += xv * w.z; acc[r][3] += xv * w.w;
        }
    }

    float a0 = attsm[lane * 4 + 0], a1 = attsm[lane * 4 + 1];
    float a2 = attsm[lane * 4 + 2], a3 = attsm[lane * 4 + 3];
    float4* feat4 = (float4*)g_feat;
    #pragma unroll
    for (int r = 0; r < RPW; r++) {
        int row = row0 + r;
        if (row >= nrows) break;
        float4 o = make_float4(acc[r][0], acc[r][1], acc[r][2], acc[r][3]);
        feat4[row * 32 + lane] = o;
        float p = o.x * a0 + o.y * a1 + o.z * a2 + o.w * a3;
        p += __shfl_xor_sync(0xffffffffu, p, 4);
        p += __shfl_xor_sync(0xffffffffu, p, 2);
        p += __shfl_xor_sync(0xffffffffu, p, 1);
        if ((lane & 7) == 0) g_asrc[row * HEADS + (lane >> 3)] = p;
    }
}

// ---------------- GEMM for dst: out = x@W_self + b; alpha_dst = x@v (fused)
__global__ __launch_bounds__(256, 2)
void gemm_dst_kernel(const float* __restrict__ x,
                     const float* __restrict__ Wself,
                     const float* __restrict__ bself,
                     float* __restrict__ out,
                     int nrows) {
    extern __shared__ float sm[];
    float* Wsm = sm;                       // 128*128
    float* bsm = sm + FDIM * FDIM;         // 128
    float* vsm = sm + FDIM * FDIM + FDIM;  // 128*4

    int tid = threadIdx.x;
    float4* Wsm4 = (float4*)Wsm;
    const float4* W4 = (const float4*)Wself;
    for (int i = tid; i < FDIM * (FDIM / 4); i += 256) Wsm4[i] = W4[i];
    if (tid < FDIM) bsm[tid] = bself[tid];
    for (int i = tid; i < FDIM * HEADS; i += 256) vsm[i] = g_v[i];
    __syncthreads();

    __shared__ float xs[GW][RPW][FDIM];
    int warp = tid >> 5, lane = tid & 31;
    int row0 = (blockIdx.x * GW + warp) * RPW;
    if (row0 >= nrows) return;

    for (int i = lane; i < RPW * FDIM; i += 32) {
        int r = i >> 7, k = i & 127;
        int row = row0 + r;
        xs[warp][r][k] = (row < nrows) ? x[row * FDIM + k] : 0.f;
    }
    __syncwarp();

    float acc[RPW][4] = {};
    float av[RPW] = {};
    #pragma unroll 4
    for (int k = 0; k < FDIM; k++) {
        float4 w = Wsm4[k * 32 + lane];
        float vv = vsm[k * HEADS + (lane & 3)];  // only lanes 0-3 meaningful
        #pragma unroll
        for (int r = 0; r < RPW; r++) {
            float xv = xs[warp][r][k];
            acc[r][0] += xv * w.x; acc[r][1] += xv * w.y;
            acc[r][2] += xv * w.z; acc[r][3] += xv * w.w;
            av[r] += xv * vv;
        }
    }

    float b0 = bsm[lane * 4 + 0], b1 = bsm[lane * 4 + 1];
    float b2 = bsm[lane * 4 + 2], b3 = bsm[lane * 4 + 3];
    float4* out4 = (float4*)out;
    #pragma unroll
    for (int r = 0; r < RPW; r++) {
        int row = row0 + r;
        if (row >= nrows) break;
        float4 o = make_float4(acc[r][0] + b0, acc[r][1] + b1,
                               acc[r][2] + b2, acc[r][3] + b3);
        out4[row * 32 + lane] = o;
        if (lane < HEADS) g_adst[row * HEADS + lane] = av[r];
    }
}

// ---------------- edge pass 1: softmax denominators
__global__ void edge_denom_kernel(const int* __restrict__ es,
                                  const int* __restrict__ ed, int E) {
    int e = blockIdx.x * blockDim.x + threadIdx.x;
    if (e >= E) return;
    int s = es[e], d = ed[e];
    const float4 as = ((const float4*)g_asrc)[s];
    const float4 ad = ((const float4*)g_adst)[d];
    float4 w;
    w.x = __expf(leaky02(as.x + ad.x));
    w.y = __expf(leaky02(as.y + ad.y));
    w.z = __expf(leaky02(as.z + ad.z));
    w.w = __expf(leaky02(as.w + ad.w));
    red_add_v4(g_asum + d * HEADS, w);
}

// ---------------- edge pass 2: weighted scatter-add of messages (warp/edge)
__global__ __launch_bounds__(256)
void edge_aggr_kernel(const int* __restrict__ es,
                      const int* __restrict__ ed,
                      float* __restrict__ out, int E) {
    int e = (blockIdx.x * blockDim.x + threadIdx.x) >> 5;
    int lane = threadIdx.x & 31;
    if (e >= E) return;
    int s = es[e], d = ed[e];
    int h = lane >> 3;
    float z = g_asrc[s * HEADS + h] + g_adst[d * HEADS + h];
    float w = __expf(leaky02(z)) / (g_asum[d * HEADS + h] + 1e-16f);
    float4 f = ((const float4*)g_feat)[s * 32 + lane];
    f.x *= w; f.y *= w; f.z *= w; f.w *= w;
    red_add_v4(out + d * FDIM + lane * 4, f);
}

// ---------------------------------------------------------------------------
extern "C" void kernel_launch(void* const* d_in, const int* in_sizes, int n_in,
                              void* d_out, int out_size) {
    const float* x_src    = (const float*)d_in[0];
    const float* x_dst    = (const float*)d_in[1];
    const int*   edge_src = (const int*)d_in[2];
    const int*   edge_dst = (const int*)d_in[3];
    int off = (n_in >= 11) ? 5 : 4;  // skip scalar num_dst if present
    const float* W_src   = (const float*)d_in[off + 0];
    const float* W_dst   = (const float*)d_in[off + 1];
    const float* att_src = (const float*)d_in[off + 2];
    const float* att_dst = (const float*)d_in[off + 3];
    const float* W_self  = (const float*)d_in[off + 4];
    const float* b_self  = (const float*)d_in[off + 5];
    float* out = (float*)d_out;

    int n_src = in_sizes[0] / FDIM;
    int n_dst = in_sizes[1] / FDIM;
    int E     = in_sizes[2];

    static bool attr_set = false;
    int smem_src = (FDIM * FDIM + FDIM) * 4;
    int smem_dst = (FDIM * FDIM + FDIM + FDIM * HEADS) * 4;
    if (!attr_set) {
        cudaFuncSetAttribute(gemm_src_kernel,
            cudaFuncAttributeMaxDynamicSharedMemorySize, smem_src);
        cudaFuncSetAttribute(gemm_dst_kernel,
            cudaFuncAttributeMaxDynamicSharedMemorySize, smem_dst);
        attr_set = true;
    }

    // 1) fold W_dst * att_dst -> v
    fold_v_kernel<<<1, 128>>>(W_dst, att_dst);

    // 2) zero softmax denominators
    int nz = n_dst * HEADS;
    zero_asum_kernel<<<(nz + 255) / 256, 256>>>(nz);

    // 3) src GEMM (feat + alpha_src)
    int blk_src = (n_src + GW * RPW - 1) / (GW * RPW);
    gemm_src_kernel<<<blk_src, 256, smem_src>>>(x_src, W_src, att_src, n_src);

    // 4) dst GEMM (out self-term + alpha_dst)
    int blk_dst = (n_dst + GW * RPW - 1) / (GW * RPW);
    gemm_dst_kernel<<<blk_dst, 256, smem_dst>>>(x_dst, W_self, b_self, out, n_dst);

    // 5) edge denominators
    edge_denom_kernel<<<(E + 255) / 256, 256>>>(edge_src, edge_dst, E);

    // 6) edge aggregation (warp per edge)
    long long total_threads = (long long)E * 32;
    int blocks = (int)((total_threads + 255) / 256);
    edge_aggr_kernel<<<blocks, 256>>>(edge_src, edge_dst, out, E);
}

// round 3
// speedup vs baseline: 1.0493x; 1.0493x over previous
#include <cuda_runtime.h>
#include <cuda_bf16.h>

// ---------------------------------------------------------------------------
// BipartiteGATConv — round 3 (round-2 design + device-symbol address fix)
//   feat   = x_src @ W_src                  (tiled GEMM, pure)
//   out    = x_dst @ W_self + b_self        (tiled GEMM, bias)
//   a_src  = x_src @ fold(W_src, att_src)   (GEMV, 128x4)
//   a_dst  = x_dst @ fold(W_dst, att_dst)   (GEMV, 128x4)
//   per-edge softmax denom + weighted scatter-add (red.global.add.v4)
// Softmax max-subtraction skipped (shift-invariant; alphas are tiny).
// ---------------------------------------------------------------------------

#define MAX_N   50000
#define FDIM    128
#define HEADS   4

__device__ __align__(16) float g_feat[MAX_N * FDIM];
__device__ __align__(16) float g_asrc[MAX_N * HEADS];
__device__ __align__(16) float g_adst[MAX_N * HEADS];
__device__ __align__(16) float g_asum[MAX_N * HEADS];
__device__ __align__(16) float g_fold_u[FDIM * HEADS];  // src fold
__device__ __align__(16) float g_fold_v[FDIM * HEADS];  // dst fold

__device__ __forceinline__ void red_add_v4(float* addr, float4 v) {
    asm volatile("red.global.add.v4.f32 [%0], {%1,%2,%3,%4};"
                 :: "l"(addr), "f"(v.x), "f"(v.y), "f"(v.z), "f"(v.w)
                 : "memory");
}

__device__ __forceinline__ float leaky02(float z) {
    return z > 0.f ? z : 0.2f * z;
}

// ---------------- fold: u[k,h] = sum_d W[k, h*32+d] * att[h*32+d]
__global__ void fold_kernel(const float* __restrict__ W_src,
                            const float* __restrict__ att_src,
                            const float* __restrict__ W_dst,
                            const float* __restrict__ att_dst) {
    int tid = threadIdx.x;     // 256 threads
    int k = tid & 127;
    const float* W   = (tid < 128) ? W_src : W_dst;
    const float* att = (tid < 128) ? att_src : att_dst;
    float* dst       = (tid < 128) ? g_fold_u : g_fold_v;
    #pragma unroll
    for (int h = 0; h < HEADS; h++) {
        float s = 0.f;
        #pragma unroll 8
        for (int d = 0; d < 32; d++)
            s += W[k * FDIM + h * 32 + d] * att[h * 32 + d];
        dst[k * HEADS + h] = s;
    }
}

__global__ void zero_asum_kernel(int n) {
    int i = blockIdx.x * blockDim.x + threadIdx.x;
    if (i < n) g_asum[i] = 0.f;
}

// ---------------- alpha GEMV: out[n,4] = x[n,128] @ fold[128,4]
// warp handles 4 rows; 8 lanes per row, 16 k each.
__global__ __launch_bounds__(256)
void alpha_kernel(const float* __restrict__ x,
                  const float* __restrict__ fold,
                  float* __restrict__ out, int n) {
    __shared__ float usm[FDIM * HEADS];
    int tid = threadIdx.x;
    usm[tid] = fold[tid];
    usm[tid + 256] = fold[tid + 256];
    __syncthreads();

    int warp = tid >> 5, lane = tid & 31;
    int row = blockIdx.x * 32 + warp * 4 + (lane >> 3);
    if (row >= n) return;
    int kbase = (lane & 7) * 16;

    const float4* xr = (const float4*)(x + (size_t)row * FDIM + kbase);
    const float4* u4base = ((const float4*)usm) + kbase;
    float4 p = make_float4(0.f, 0.f, 0.f, 0.f);
    #pragma unroll
    for (int j = 0; j < 4; j++) {
        float4 xv = xr[j];
        float4 u0 = u4base[j * 4 + 0];
        float4 u1 = u4base[j * 4 + 1];
        float4 u2 = u4base[j * 4 + 2];
        float4 u3 = u4base[j * 4 + 3];
        p.x += xv.x * u0.x + xv.y * u1.x + xv.z * u2.x + xv.w * u3.x;
        p.y += xv.x * u0.y + xv.y * u1.y + xv.z * u2.y + xv.w * u3.y;
        p.z += xv.x * u0.z + xv.y * u1.z + xv.z * u2.z + xv.w * u3.z;
        p.w += xv.x * u0.w + xv.y * u1.w + xv.z * u2.w + xv.w * u3.w;
    }
    #pragma unroll
    for (int m = 4; m >= 1; m >>= 1) {
        p.x += __shfl_xor_sync(0xffffffffu, p.x, m);
        p.y += __shfl_xor_sync(0xffffffffu, p.y, m);
        p.z += __shfl_xor_sync(0xffffffffu, p.z, m);
        p.w += __shfl_xor_sync(0xffffffffu, p.w, m);
    }
    if ((lane & 7) == 0) ((float4*)out)[row] = p;
}

// ---------------- tiled GEMM: C[n,128] = A[n,128] @ B[128,128] (+bias)
#define BM 128
#define BN 128
#define BK 16
#define TM 8
#define TN 8

__global__ __launch_bounds__(256, 2)
void gemm128_kernel(const float* __restrict__ A,
                    const float* __restrict__ B,
                    const float* __restrict__ bias,
                    float* __restrict__ C,
                    int nrows, int use_bias) {
    __shared__ float As[2][BK][BM];
    __shared__ float Bs[2][BK][BN];

    int tid = threadIdx.x;
    int tn_idx = tid & 15;
    int tm_idx = tid >> 4;
    int tm0 = tm_idx * TM;
    int tn0 = tn_idx * TN;
    int m0 = blockIdx.x * BM;

    float acc[TM][TN];
    #pragma unroll
    for (int i = 0; i < TM; i++)
        #pragma unroll
        for (int j = 0; j < TN; j++) acc[i][j] = 0.f;

    int af_row[2], af_k4[2];
    int bf_k[2], bf_n4[2];
    #pragma unroll
    for (int i = 0; i < 2; i++) {
        int f = tid + i * 256;
        af_row[i] = f >> 2;
        af_k4[i]  = (f & 3) * 4;
        bf_k[i]   = f >> 5;
        bf_n4[i]  = (f & 31) * 4;
    }

    float4 a_reg[2], b_reg[2];
    const float4 zero4 = make_float4(0.f, 0.f, 0.f, 0.f);

    #pragma unroll
    for (int i = 0; i < 2; i++) {
        int grow = m0 + af_row[i];
        a_reg[i] = (grow < nrows)
            ? *(const float4*)(A + (size_t)grow * FDIM + af_k4[i]) : zero4;
        b_reg[i] = *(const float4*)(B + (size_t)bf_k[i] * FDIM + bf_n4[i]);
    }
    #pragma unroll
    for (int i = 0; i < 2; i++) {
        As[0][af_k4[i] + 0][af_row[i]] = a_reg[i].x;
        As[0][af_k4[i] + 1][af_row[i]] = a_reg[i].y;
        As[0][af_k4[i] + 2][af_row[i]] = a_reg[i].z;
        As[0][af_k4[i] + 3][af_row[i]] = a_reg[i].w;
        *(float4*)&Bs[0][bf_k[i]][bf_n4[i]] = b_reg[i];
    }
    __syncthreads();

    int buf = 0;
    const int NT = FDIM / BK;  // 8 tiles
    for (int t = 0; t < NT; t++) {
        if (t + 1 < NT) {
            int kt = (t + 1) * BK;
            #pragma unroll
            for (int i = 0; i < 2; i++) {
                int grow = m0 + af_row[i];
                a_reg[i] = (grow < nrows)
                    ? *(const float4*)(A + (size_t)grow * FDIM + kt + af_k4[i]) : zero4;
                b_reg[i] = *(const float4*)(B + (size_t)(kt + bf_k[i]) * FDIM + bf_n4[i]);
            }
        }

        #pragma unroll
        for (int k = 0; k < BK; k++) {
            float4 a0 = *(const float4*)&As[buf][k][tm0];
            float4 a1 = *(const float4*)&As[buf][k][tm0 + 4];
            float4 b0 = *(const float4*)&Bs[buf][k][tn0];
            float4 b1 = *(const float4*)&Bs[buf][k][tn0 + 4];
            float av[TM] = {a0.x, a0.y, a0.z, a0.w, a1.x, a1.y, a1.z, a1.w};
            float bv[TN] = {b0.x, b0.y, b0.z, b0.w, b1.x, b1.y, b1.z, b1.w};
            #pragma unroll
            for (int i = 0; i < TM; i++)
                #pragma unroll
                for (int j = 0; j < TN; j++)
                    acc[i][j] += av[i] * bv[j];
        }

        if (t + 1 < NT) {
            int nb = buf ^ 1;
            #pragma unroll
            for (int i = 0; i < 2; i++) {
                As[nb][af_k4[i] + 0][af_row[i]] = a_reg[i].x;
                As[nb][af_k4[i] + 1][af_row[i]] = a_reg[i].y;
                As[nb][af_k4[i] + 2][af_row[i]] = a_reg[i].z;
                As[nb][af_k4[i] + 3][af_row[i]] = a_reg[i].w;
                *(float4*)&Bs[nb][bf_k[i]][bf_n4[i]] = b_reg[i];
            }
            __syncthreads();
            buf = nb;
        }
    }

    float4 bb0 = zero4, bb1 = zero4;
    if (use_bias) {
        bb0 = *(const float4*)(bias + tn0);
        bb1 = *(const float4*)(bias + tn0 + 4);
    }
    #pragma unroll
    for (int i = 0; i < TM; i++) {
        int row = m0 + tm0 + i;
        if (row < nrows) {
            float4 o0 = make_float4(acc[i][0] + bb0.x, acc[i][1] + bb0.y,
                                    acc[i][2] + bb0.z, acc[i][3] + bb0.w);
            float4 o1 = make_float4(acc[i][4] + bb1.x, acc[i][5] + bb1.y,
                                    acc[i][6] + bb1.z, acc[i][7] + bb1.w);
            *(float4*)(C + (size_t)row * FDIM + tn0)     = o0;
            *(float4*)(C + (size_t)row * FDIM + tn0 + 4) = o1;
        }
    }
}

// ---------------- edge pass 1: softmax denominators
__global__ void edge_denom_kernel(const int* __restrict__ es,
                                  const int* __restrict__ ed, int E) {
    int e = blockIdx.x * blockDim.x + threadIdx.x;
    if (e >= E) return;
    int s = es[e], d = ed[e];
    const float4 as = ((const float4*)g_asrc)[s];
    const float4 ad = ((const float4*)g_adst)[d];
    float4 w;
    w.x = __expf(leaky02(as.x + ad.x));
    w.y = __expf(leaky02(as.y + ad.y));
    w.z = __expf(leaky02(as.z + ad.z));
    w.w = __expf(leaky02(as.w + ad.w));
    red_add_v4(g_asum + d * HEADS, w);
}

// ---------------- edge pass 2: weighted scatter-add of messages (warp/edge)
__global__ __launch_bounds__(256)
void edge_aggr_kernel(const int* __restrict__ es,
                      const int* __restrict__ ed,
                      float* __restrict__ out, int E) {
    int e = (blockIdx.x * blockDim.x + threadIdx.x) >> 5;
    int lane = threadIdx.x & 31;
    if (e >= E) return;
    int s = es[e], d = ed[e];
    int h = lane >> 3;
    float z = g_asrc[s * HEADS + h] + g_adst[d * HEADS + h];
    float w = __expf(leaky02(z)) / (g_asum[d * HEADS + h] + 1e-16f);
    float4 f = ((const float4*)g_feat)[s * 32 + lane];
    f.x *= w; f.y *= w; f.z *= w; f.w *= w;
    red_add_v4(out + d * FDIM + lane * 4, f);
}

// ---------------------------------------------------------------------------
extern "C" void kernel_launch(void* const* d_in, const int* in_sizes, int n_in,
                              void* d_out, int out_size) {
    const float* x_src    = (const float*)d_in[0];
    const float* x_dst    = (const float*)d_in[1];
    const int*   edge_src = (const int*)d_in[2];
    const int*   edge_dst = (const int*)d_in[3];
    int off = (n_in >= 11) ? 5 : 4;  // skip scalar num_dst if present
    const float* W_src   = (const float*)d_in[off + 0];
    const float* W_dst   = (const float*)d_in[off + 1];
    const float* att_src = (const float*)d_in[off + 2];
    const float* att_dst = (const float*)d_in[off + 3];
    const float* W_self  = (const float*)d_in[off + 4];
    const float* b_self  = (const float*)d_in[off + 5];
    float* out = (float*)d_out;

    int n_src = in_sizes[0] / FDIM;
    int n_dst = in_sizes[1] / FDIM;
    int E     = in_sizes[2];

    // Resolve real device addresses of __device__ globals (host shadow symbols
    // are NOT device pointers — passing them as kernel args is the round-2 bug).
    static float* p_feat = nullptr;
    static float* p_asrc = nullptr;
    static float* p_adst = nullptr;
    static float* p_fold_u = nullptr;
    static float* p_fold_v = nullptr;
    if (!p_feat) {
        cudaGetSymbolAddress((void**)&p_feat,   g_feat);
        cudaGetSymbolAddress((void**)&p_asrc,   g_asrc);
        cudaGetSymbolAddress((void**)&p_adst,   g_adst);
        cudaGetSymbolAddress((void**)&p_fold_u, g_fold_u);
        cudaGetSymbolAddress((void**)&p_fold_v, g_fold_v);
    }

    // 1) folds
    fold_kernel<<<1, 256>>>(W_src, att_src, W_dst, att_dst);

    // 2) zero softmax denominators
    int nz = n_dst * HEADS;
    zero_asum_kernel<<<(nz + 255) / 256, 256>>>(nz);

    // 3) alpha GEMVs
    alpha_kernel<<<(n_src + 31) / 32, 256>>>(x_src, p_fold_u, p_asrc, n_src);
    alpha_kernel<<<(n_dst + 31) / 32, 256>>>(x_dst, p_fold_v, p_adst, n_dst);

    // 4) GEMMs
    gemm128_kernel<<<(n_src + BM - 1) / BM, 256>>>(x_src, W_src, b_self,
                                                   p_feat, n_src, 0);
    gemm128_kernel<<<(n_dst + BM - 1) / BM, 256>>>(x_dst, W_self, b_self,
                                                   out, n_dst, 1);

    // 5) edge denominators
    edge_denom_kernel<<<(E + 255) / 256, 256>>>(edge_src, edge_dst, E);

    // 6) edge aggregation (warp per edge)
    long long total_threads = (long long)E * 32;
    int blocks = (int)((total_threads + 255) / 256);
    edge_aggr_kernel<<<blocks, 256>>>(edge_src, edge_dst, out, E);
}

// round 4
// speedup vs baseline: 1.4143x; 1.3478x over previous
#include <cuda_runtime.h>
#include <cuda_bf16.h>

// ---------------------------------------------------------------------------
// BipartiteGATConv — round 4
//   feat + alpha_src : fused src GEMM (alpha from accumulator epilogue)
//   out  + alpha_dst : fused dst GEMM (alpha_dst = x@fold(W_dst,att) in mainloop)
//   per-edge softmax denom + weighted scatter-add (red.global.add.v4)
// Softmax max-subtraction skipped (shift-invariant; alphas are tiny).
// ---------------------------------------------------------------------------

#define MAX_N   50000
#define FDIM    128
#define HEADS   4

__device__ __align__(16) float g_feat[MAX_N * FDIM];
__device__ __align__(16) float g_asrc[MAX_N * HEADS];
__device__ __align__(16) float g_adst[MAX_N * HEADS];
__device__ __align__(16) float g_asum[MAX_N * HEADS];
__device__ __align__(16) float g_fold_v[FDIM * HEADS];  // dst fold

__device__ __forceinline__ void red_add_v4(float* addr, float4 v) {
    asm volatile("red.global.add.v4.f32 [%0], {%1,%2,%3,%4};"
                 :: "l"(addr), "f"(v.x), "f"(v.y), "f"(v.z), "f"(v.w)
                 : "memory");
}

__device__ __forceinline__ float leaky02(float z) {
    return z > 0.f ? z : 0.2f * z;
}

// ---------------- fold: v[k,h] = sum_d W_dst[k, h*32+d] * att_dst[h*32+d]
__global__ void fold_kernel(const float* __restrict__ W_dst,
                            const float* __restrict__ att_dst) {
    int k = threadIdx.x;   // 128 threads
    #pragma unroll
    for (int h = 0; h < HEADS; h++) {
        float s = 0.f;
        #pragma unroll 8
        for (int d = 0; d < 32; d++)
            s += W_dst[k * FDIM + h * 32 + d] * att_dst[h * 32 + d];
        g_fold_v[k * HEADS + h] = s;
    }
}

__global__ void zero_asum_kernel(int n) {
    int i = blockIdx.x * blockDim.x + threadIdx.x;
    if (i < n) g_asum[i] = 0.f;
}

// ---------------- tiled GEMM: 128-wide, BM=128, BK=16, TM=TN=8
#define BM 128
#define BN 128
#define BK 16
#define TM 8
#define TN 8

// MODE 0: feat GEMM + alpha_src epilogue (att in smem)
// MODE 1: out GEMM + bias + alpha_dst in mainloop (fold_v in smem)
template <int MODE>
__global__ __launch_bounds__(256, 2)
void gemm128_kernel(const float* __restrict__ A,
                    const float* __restrict__ B,
                    const float* __restrict__ aux,   // att_src (M0) / bias (M1)
                    float* __restrict__ C,
                    float* __restrict__ alpha_out,
                    int nrows) {
    __shared__ float As[2][BK][BM];
    __shared__ float Bs[2][BK][BN];
    __shared__ float xtra[MODE == 0 ? FDIM : FDIM * HEADS];

    int tid = threadIdx.x;
    int tn_idx = tid & 15;
    int tm_idx = tid >> 4;
    int tm0 = tm_idx * TM;
    int tn0 = tn_idx * TN;
    int m0 = blockIdx.x * BM;

    if (MODE == 0) {
        if (tid < FDIM) xtra[tid] = aux[tid];   // att_src, layout [h*32+d]
    } else {
        xtra[tid] = g_fold_v[tid];
        xtra[tid + 256] = g_fold_v[tid + 256];
    }

    float acc[TM][TN];
    #pragma unroll
    for (int i = 0; i < TM; i++)
        #pragma unroll
        for (int j = 0; j < TN; j++) acc[i][j] = 0.f;

    int af_row[2], af_k4[2];
    int bf_k[2], bf_n4[2];
    #pragma unroll
    for (int i = 0; i < 2; i++) {
        int f = tid + i * 256;
        af_row[i] = f >> 2;
        af_k4[i]  = (f & 3) * 4;
        bf_k[i]   = f >> 5;
        bf_n4[i]  = (f & 31) * 4;
    }

    float4 a_reg[2], b_reg[2];
    const float4 zero4 = make_float4(0.f, 0.f, 0.f, 0.f);

    #pragma unroll
    for (int i = 0; i < 2; i++) {
        int grow = m0 + af_row[i];
        a_reg[i] = (grow < nrows)
            ? *(const float4*)(A + (size_t)grow * FDIM + af_k4[i]) : zero4;
        b_reg[i] = *(const float4*)(B + (size_t)bf_k[i] * FDIM + bf_n4[i]);
    }
    #pragma unroll
    for (int i = 0; i < 2; i++) {
        As[0][af_k4[i] + 0][af_row[i]] = a_reg[i].x;
        As[0][af_k4[i] + 1][af_row[i]] = a_reg[i].y;
        As[0][af_k4[i] + 2][af_row[i]] = a_reg[i].z;
        As[0][af_k4[i] + 3][af_row[i]] = a_reg[i].w;
        *(float4*)&Bs[0][bf_k[i]][bf_n4[i]] = b_reg[i];
    }
    __syncthreads();

    // alpha_dst partition (MODE 1): head h, 2 rows starting at tm0+qq
    int h  = tn_idx >> 2;
    int qq = (tn_idx & 3) * 2;
    float av0 = 0.f, av1 = 0.f;

    int buf = 0;
    const int NT = FDIM / BK;  // 8 tiles
    for (int t = 0; t < NT; t++) {
        if (t + 1 < NT) {
            int kt = (t + 1) * BK;
            #pragma unroll
            for (int i = 0; i < 2; i++) {
                int grow = m0 + af_row[i];
                a_reg[i] = (grow < nrows)
                    ? *(const float4*)(A + (size_t)grow * FDIM + kt + af_k4[i]) : zero4;
                b_reg[i] = *(const float4*)(B + (size_t)(kt + bf_k[i]) * FDIM + bf_n4[i]);
            }
        }

        #pragma unroll
        for (int k = 0; k < BK; k++) {
            float4 a0 = *(const float4*)&As[buf][k][tm0];
            float4 a1 = *(const float4*)&As[buf][k][tm0 + 4];
            float4 b0 = *(const float4*)&Bs[buf][k][tn0];
            float4 b1 = *(const float4*)&Bs[buf][k][tn0 + 4];
            float avv[TM] = {a0.x, a0.y, a0.z, a0.w, a1.x, a1.y, a1.z, a1.w};
            float bvv[TN] = {b0.x, b0.y, b0.z, b0.w, b1.x, b1.y, b1.z, b1.w};
            #pragma unroll
            for (int i = 0; i < TM; i++)
                #pragma unroll
                for (int j = 0; j < TN; j++)
                    acc[i][j] += avv[i] * bvv[j];
            if (MODE == 1) {
                float vv = xtra[(t * BK + k) * HEADS + h];
                av0 += As[buf][k][tm0 + qq]     * vv;
                av1 += As[buf][k][tm0 + qq + 1] * vv;
            }
        }

        if (t + 1 < NT) {
            int nb = buf ^ 1;
            #pragma unroll
            for (int i = 0; i < 2; i++) {
                As[nb][af_k4[i] + 0][af_row[i]] = a_reg[i].x;
                As[nb][af_k4[i] + 1][af_row[i]] = a_reg[i].y;
                As[nb][af_k4[i] + 2][af_row[i]] = a_reg[i].z;
                As[nb][af_k4[i] + 3][af_row[i]] = a_reg[i].w;
                *(float4*)&Bs[nb][bf_k[i]][bf_n4[i]] = b_reg[i];
            }
            __syncthreads();
            buf = nb;
        }
    }

    // epilogue: bias (MODE 1)
    float4 bb0 = zero4, bb1 = zero4;
    if (MODE == 1) {
        bb0 = *(const float4*)(aux + tn0);
        bb1 = *(const float4*)(aux + tn0 + 4);
    }
    #pragma unroll
    for (int i = 0; i < TM; i++) {
        int row = m0 + tm0 + i;
        if (row < nrows) {
            float4 o0 = make_float4(acc[i][0] + bb0.x, acc[i][1] + bb0.y,
                                    acc[i][2] + bb0.z, acc[i][3] + bb0.w);
            float4 o1 = make_float4(acc[i][4] + bb1.x, acc[i][5] + bb1.y,
                                    acc[i][6] + bb1.z, acc[i][7] + bb1.w);
            *(float4*)(C + (size_t)row * FDIM + tn0)     = o0;
            *(float4*)(C + (size_t)row * FDIM + tn0 + 4) = o1;
        }
    }

    if (MODE == 0) {
        // alpha_src: p[i] = sum_j acc[i][j]*att[tn0+j]; reduce 4 threads/head
        float a_att[TN];
        #pragma unroll
        for (int j = 0; j < TN; j++) a_att[j] = xtra[tn0 + j];
        #pragma unroll
        for (int i = 0; i < TM; i++) {
            float p = 0.f;
            #pragma unroll
            for (int j = 0; j < TN; j++) p += acc[i][j] * a_att[j];
            p += __shfl_xor_sync(0xffffffffu, p, 1);
            p += __shfl_xor_sync(0xffffffffu, p, 2);
            if ((tn_idx & 3) == 0) {
                int row = m0 + tm0 + i;
                if (row < nrows) alpha_out[row * HEADS + h] = p;
            }
        }
    } else {
        // alpha_dst: each thread owns 2 rows of one head
        int r0 = m0 + tm0 + qq;
        if (r0 < nrows)     alpha_out[r0 * HEADS + h]       = av0;
        if (r0 + 1 < nrows) alpha_out[(r0 + 1) * HEADS + h] = av1;
    }
}

// ---------------- edge pass 1: softmax denominators
__global__ void edge_denom_kernel(const int* __restrict__ es,
                                  const int* __restrict__ ed, int E) {
    int e = blockIdx.x * blockDim.x + threadIdx.x;
    if (e >= E) return;
    int s = es[e], d = ed[e];
    const float4 as = ((const float4*)g_asrc)[s];
    const float4 ad = ((const float4*)g_adst)[d];
    float4 w;
    w.x = __expf(leaky02(as.x + ad.x));
    w.y = __expf(leaky02(as.y + ad.y));
    w.z = __expf(leaky02(as.z + ad.z));
    w.w = __expf(leaky02(as.w + ad.w));
    red_add_v4(g_asum + d * HEADS, w);
}

// ---------------- edge pass 2: weighted scatter-add of messages (warp/edge)
__global__ __launch_bounds__(256)
void edge_aggr_kernel(const int* __restrict__ es,
                      const int* __restrict__ ed,
                      float* __restrict__ out, int E) {
    int e = (blockIdx.x * blockDim.x + threadIdx.x) >> 5;
    int lane = threadIdx.x & 31;
    if (e >= E) return;
    int s = es[e], d = ed[e];
    int h = lane >> 3;
    float z = g_asrc[s * HEADS + h] + g_adst[d * HEADS + h];
    float w = __expf(leaky02(z)) / (g_asum[d * HEADS + h] + 1e-16f);
    float4 f = ((const float4*)g_feat)[s * 32 + lane];
    f.x *= w; f.y *= w; f.z *= w; f.w *= w;
    red_add_v4(out + d * FDIM + lane * 4, f);
}

// ---------------------------------------------------------------------------
extern "C" void kernel_launch(void* const* d_in, const int* in_sizes, int n_in,
                              void* d_out, int out_size) {
    const float* x_src    = (const float*)d_in[0];
    const float* x_dst    = (const float*)d_in[1];
    const int*   edge_src = (const int*)d_in[2];
    const int*   edge_dst = (const int*)d_in[3];
    int off = (n_in >= 11) ? 5 : 4;  // skip scalar num_dst if present
    const float* W_src   = (const float*)d_in[off + 0];
    const float* W_dst   = (const float*)d_in[off + 1];
    const float* att_src = (const float*)d_in[off + 2];
    const float* att_dst = (const float*)d_in[off + 3];
    const float* W_self  = (const float*)d_in[off + 4];
    const float* b_self  = (const float*)d_in[off + 5];
    float* out = (float*)d_out;

    int n_src = in_sizes[0] / FDIM;
    int n_dst = in_sizes[1] / FDIM;
    int E     = in_sizes[2];

    static float* p_feat = nullptr;
    static float* p_asrc = nullptr;
    static float* p_adst = nullptr;
    if (!p_feat) {
        cudaGetSymbolAddress((void**)&p_feat, g_feat);
        cudaGetSymbolAddress((void**)&p_asrc, g_asrc);
        cudaGetSymbolAddress((void**)&p_adst, g_adst);
    }

    // 1) fold for alpha_dst
    fold_kernel<<<1, 128>>>(W_dst, att_dst);

    // 2) zero softmax denominators
    int nz = n_dst * HEADS;
    zero_asum_kernel<<<(nz + 255) / 256, 256>>>(nz);

    // 3) fused GEMMs
    gemm128_kernel<0><<<(n_src + BM - 1) / BM, 256>>>(
        x_src, W_src, att_src, p_feat, p_asrc, n_src);
    gemm128_kernel<1><<<(n_dst + BM - 1) / BM, 256>>>(
        x_dst, W_self, b_self, out, p_adst, n_dst);

    // 4) edge denominators
    edge_denom_kernel<<<(E + 255) / 256, 256>>>(edge_src, edge_dst, E);

    // 5) edge aggregation (warp per edge)
    long long total_threads = (long long)E * 32;
    int blocks = (int)((total_threads + 255) / 256);
    edge_aggr_kernel<<<blocks, 256>>>(edge_src, edge_dst, out, E);
}